// round 15
// baseline (speedup 1.0000x reference)
#include <cuda_runtime.h>
#include <cstdint>

#define HB 768
#define N2 6144
#define D2 1536
#define RECB 128
#define REC2T 256
#define SENT 0x7FC00001u

// ----------------------------- scratch (device globals; allocation-free) ----
__device__ float g_pre [1024 * N2];
__device__ float g_hseq[1024 * D2];   // raw-h sequence: comm + layer output
__device__ float g_seqA[1024 * D2];   // tanh(h) of layer 2
__device__ float g_hq  [256 * HB];
__device__ float g_hk  [1024 * HB];
__device__ float g_P   [256 * 256];
__device__ float g_sf  [256 * D2];
__device__ float g_tmpT[256 * 2304];
__device__ float g_adv [256 * 3];

// ---------------------------------------------------------------------------
// TF32 tensor-core GEMM 128x128x16: C = A @ B^T (+bias). Double-buffered
// (R10-proven body, 190us verified).
// ---------------------------------------------------------------------------
__device__ __forceinline__ uint32_t f2tf32(float f)
{
    uint32_t u;
    asm("cvt.rna.tf32.f32 %0, %1;" : "=r"(u) : "f"(f));
    return u;
}
__device__ __forceinline__ void mma_tf32(float* c, const uint32_t* a,
                                         uint32_t b0, uint32_t b1)
{
    asm volatile(
        "mma.sync.aligned.m16n8k8.row.col.f32.tf32.tf32.f32 "
        "{%0,%1,%2,%3}, {%4,%5,%6,%7}, {%8,%9}, {%0,%1,%2,%3};\n"
        : "+f"(c[0]), "+f"(c[1]), "+f"(c[2]), "+f"(c[3])
        : "r"(a[0]), "r"(a[1]), "r"(a[2]), "r"(a[3]), "r"(b0), "r"(b1));
}

__global__ __launch_bounds__(256, 2)
void tf32gemm_abT(const float* __restrict__ A, int lda,
                  const float* __restrict__ B, int ldb,
                  const float* __restrict__ bias,
                  float* __restrict__ C, int ldc, int K)
{
    __shared__ uint32_t As[2][16][136];
    __shared__ uint32_t Bs[2][16][136];
    const int tid = threadIdx.x;
    const int m0 = blockIdx.y * 128, n0 = blockIdx.x * 128;
    const int warp = tid >> 5, lane = tid & 31;
    const int wm = warp >> 1, wn = warp & 1;
    const int gid = lane >> 2, tig = lane & 3;
    const int lrow = tid >> 2, lk = (tid & 3) * 4;
    const int sxor = ((lk >> 2) & 3) << 3;
    const int c0a = lrow ^ sxor, c1a = (64 + lrow) ^ sxor;

    float c[2][8][4];
#pragma unroll
    for (int mt = 0; mt < 2; mt++)
#pragma unroll
        for (int nt = 0; nt < 8; nt++)
#pragma unroll
            for (int q = 0; q < 4; q++) c[mt][nt][q] = 0.f;

    const float* Ap0 = A + (size_t)(m0 + lrow) * lda + lk;
    const float* Ap1 = A + (size_t)(m0 + 64 + lrow) * lda + lk;
    const float* Bp0 = B + (size_t)(n0 + lrow) * ldb + lk;
    const float* Bp1 = B + (size_t)(n0 + 64 + lrow) * ldb + lk;

#define STAGE(BUF, A0, A1, B0, B1) do {                                    \
    As[BUF][lk+0][c0a] = f2tf32(A0.x); As[BUF][lk+1][c0a] = f2tf32(A0.y);  \
    As[BUF][lk+2][c0a] = f2tf32(A0.z); As[BUF][lk+3][c0a] = f2tf32(A0.w);  \
    As[BUF][lk+0][c1a] = f2tf32(A1.x); As[BUF][lk+1][c1a] = f2tf32(A1.y);  \
    As[BUF][lk+2][c1a] = f2tf32(A1.z); As[BUF][lk+3][c1a] = f2tf32(A1.w);  \
    Bs[BUF][lk+0][c0a] = f2tf32(B0.x); Bs[BUF][lk+1][c0a] = f2tf32(B0.y);  \
    Bs[BUF][lk+2][c0a] = f2tf32(B0.z); Bs[BUF][lk+3][c0a] = f2tf32(B0.w);  \
    Bs[BUF][lk+0][c1a] = f2tf32(B1.x); Bs[BUF][lk+1][c1a] = f2tf32(B1.y);  \
    Bs[BUF][lk+2][c1a] = f2tf32(B1.z); Bs[BUF][lk+3][c1a] = f2tf32(B1.w);  \
} while (0)

    float4 a0 = *(const float4*)(Ap0);
    float4 a1 = *(const float4*)(Ap1);
    float4 b0 = *(const float4*)(Bp0);
    float4 b1 = *(const float4*)(Bp1);
    STAGE(0, a0, a1, b0, b1);
    __syncthreads();

    const int nT = K >> 4;
    for (int t = 0; t < nT; t++) {
        const int buf = t & 1;
        if (t + 1 < nT) {
            const int k0 = (t + 1) << 4;
            a0 = *(const float4*)(Ap0 + k0);
            a1 = *(const float4*)(Ap1 + k0);
            b0 = *(const float4*)(Bp0 + k0);
            b1 = *(const float4*)(Bp1 + k0);
        }
#pragma unroll
        for (int ks = 0; ks < 2; ks++) {
            const int r0 = ks * 8 + tig;
            const int r1 = ks * 8 + 4 + tig;
            const int x0 = ((r0 >> 2) & 3) << 3;
            const int x1 = ((r1 >> 2) & 3) << 3;
            uint32_t af[2][4];
#pragma unroll
            for (int mt = 0; mt < 2; mt++) {
                const int mb = wm * 32 + mt * 16;
                af[mt][0] = As[buf][r0][(mb + gid) ^ x0];
                af[mt][1] = As[buf][r0][(mb + 8 + gid) ^ x0];
                af[mt][2] = As[buf][r1][(mb + gid) ^ x1];
                af[mt][3] = As[buf][r1][(mb + 8 + gid) ^ x1];
            }
#pragma unroll
            for (int nt = 0; nt < 8; nt++) {
                const int nb = wn * 64 + nt * 8;
                uint32_t bf0 = Bs[buf][r0][(nb + gid) ^ x0];
                uint32_t bf1 = Bs[buf][r1][(nb + gid) ^ x1];
                mma_tf32(c[0][nt], af[0], bf0, bf1);
                mma_tf32(c[1][nt], af[1], bf0, bf1);
            }
        }
        if (t + 1 < nT) {
            STAGE(buf ^ 1, a0, a1, b0, b1);
            __syncthreads();
        }
    }
#undef STAGE

#pragma unroll
    for (int mt = 0; mt < 2; mt++) {
        const int row = m0 + wm * 32 + mt * 16 + gid;
#pragma unroll
        for (int nt = 0; nt < 8; nt++) {
            const int col = n0 + wn * 64 + nt * 8 + tig * 2;
            float bv0 = bias ? bias[col] : 0.f;
            float bv1 = bias ? bias[col + 1] : 0.f;
            float2 v0 = make_float2(c[mt][nt][0] + bv0, c[mt][nt][1] + bv1);
            float2 v1 = make_float2(c[mt][nt][2] + bv0, c[mt][nt][3] + bv1);
            *(float2*)&C[(size_t)row * ldc + col] = v0;
            *(float2*)&C[(size_t)(row + 8) * ldc + col] = v1;
        }
    }
}

// ---------------------------------------------------------------------------
// Batched GEMM 64x64x16: C = A @ B (for P @ out).
// ---------------------------------------------------------------------------
__global__ __launch_bounds__(256)
void gemm_ab64(const float* __restrict__ Ab, int lda, size_t strA,
               const float* __restrict__ Bb, int ldb, size_t strB,
               float* __restrict__ Cb, int ldc, size_t strC, int K)
{
    const float* A = Ab + strA * blockIdx.z;
    const float* B = Bb + strB * blockIdx.z;
    float* C = Cb + strC * blockIdx.z;
    __shared__ float As[16][68];
    __shared__ float Bs[16][68];
    const int tid = threadIdx.x;
    const int m0 = blockIdx.y * 64, n0 = blockIdx.x * 64;
    const int tx = tid & 15, ty = tid >> 4;
    const int lrow = tid >> 2, lk = (tid & 3) * 4;
    const int bkk = tid >> 4, bnq = (tid & 15) * 4;

    float acc[4][4];
#pragma unroll
    for (int i = 0; i < 4; i++)
#pragma unroll
        for (int j = 0; j < 4; j++) acc[i][j] = 0.f;

    for (int k0 = 0; k0 < K; k0 += 16) {
        float4 a0 = *(const float4*)&A[(size_t)(m0 + lrow) * lda + k0 + lk];
        float4 b0 = *(const float4*)&B[(size_t)(k0 + bkk) * ldb + n0 + bnq];
        __syncthreads();
        As[lk+0][lrow]=a0.x; As[lk+1][lrow]=a0.y; As[lk+2][lrow]=a0.z; As[lk+3][lrow]=a0.w;
        *(float4*)&Bs[bkk][bnq] = b0;
        __syncthreads();
#pragma unroll
        for (int kk = 0; kk < 16; kk++) {
            float ar[4], br[4];
            *(float4*)&ar[0] = *(const float4*)&As[kk][ty * 4];
            *(float4*)&br[0] = *(const float4*)&Bs[kk][tx * 4];
#pragma unroll
            for (int i = 0; i < 4; i++)
#pragma unroll
                for (int j = 0; j < 4; j++) acc[i][j] += ar[i] * br[j];
        }
    }
#pragma unroll
    for (int i = 0; i < 4; i++) {
        float4 v = make_float4(acc[i][0], acc[i][1], acc[i][2], acc[i][3]);
        *(float4*)&C[(size_t)(m0 + ty * 4 + i) * ldc + n0 + tx * 4] = v;
    }
}

// ---------------------------------------------------------------------------
__global__ void poison_kernel(float4* __restrict__ p, int n4)
{
    int i = blockIdx.x * blockDim.x + threadIdx.x;
    float s = __uint_as_float(SENT);
    if (i < n4) p[i] = make_float4(s, s, s, s);
}

// ---------------------------------------------------------------------------
// Persistent BiLSTM recurrence v5 (R10-proven structure, byte-identical
// except MUFU transcendentals in the gate path).
// 128 CTAs x 256 thr (8 warps). CTA: dir = bx>>6, cells [c0,c0+12).
// Row r = g*12 + cell (48 rows). Warp w owns rows [6w, 6w+6); lane ks holds
// k-chunks {j*128 + ks*4} -> wreg[6][6] float4 = 144 regs (cap 255 @256thr).
// Poll: uniform 3 float4s/thread over all 256 threads (proven optimal).
// ---------------------------------------------------------------------------
__device__ __forceinline__ float sigf(float x)
{
    return __fdividef(1.f, 1.f + __expf(-x));
}
__device__ __forceinline__ float tanh_fast(float x)
{
    return __fdividef(2.f, 1.f + __expf(-2.f * x)) - 1.f;
}

__device__ __forceinline__ float4 ldcg4(const float* p)
{
    float4 v;
    asm volatile("ld.global.cg.v4.f32 {%0,%1,%2,%3}, [%4];"
                 : "=f"(v.x), "=f"(v.y), "=f"(v.z), "=f"(v.w) : "l"(p));
    return v;
}
__device__ __forceinline__ bool valid4(float4 v)
{
    return (__float_as_uint(v.x) != SENT) & (__float_as_uint(v.y) != SENT) &
           (__float_as_uint(v.z) != SENT) & (__float_as_uint(v.w) != SENT);
}

__global__ __launch_bounds__(REC2T, 1)
void rec_kernel(const float* __restrict__ pre,   // [1024][6144]
                const float* __restrict__ whh,   // [2][3072][768]
                float* __restrict__ hseq,        // [1024][1536] raw h (poisoned)
                float* __restrict__ out2,        // tanh(h) when do_tanh
                int T, int do_tanh)
{
    __shared__ float sh[2][4 * 768];
    __shared__ float sgates[48 * 4];

    const int tid = threadIdx.x;
    const int bx  = blockIdx.x;
    const int dir = bx >> 6;
    const int c0  = (bx & 63) * 12;
    const int w   = tid >> 5, ks = tid & 31;

    // weights -> registers: warp w owns rows 6w..6w+5 (row = g*12+cell);
    // lane ks holds k = j*128 + ks*4 .. +3 for j=0..5.
    float4 wreg[6][6];
#pragma unroll
    for (int i = 0; i < 6; i++) {
        const int r = 6 * w + i;
        const int g = r / 12, jj = r - g * 12;
        const float* wp = whh + ((size_t)dir * 3072 + g * 768 + c0 + jj) * 768;
#pragma unroll
        for (int j = 0; j < 6; j++)
            wreg[i][j] = *(const float4*)(wp + j * 128 + ks * 4);
    }

    // poll assignment: 768 float4s of h (4 batches x 192), 3 per thread
    int pb[3], pj[3];
#pragma unroll
    for (int q = 0; q < 3; q++) {
        int f = tid + q * REC2T;
        pb[q] = f / 192;
        pj[q] = (f - pb[q] * 192) * 4;
    }

    // update-thread identity (tid < 48): cell = tid>>2, batch = tid&3
    const int ucell = tid >> 2, ub = tid & 3;

    float creg = 0.f;
    for (int step = 0; step < T; step++) {
        const int t  = (dir == 0) ? step : (T - 1 - step);
        const int tp = (dir == 0) ? t - 1 : t + 1;
        float* shb = sh[step & 1];

        // update threads prefetch their own pre-activations (4 gates)
        float pg0 = 0.f, pg1 = 0.f, pg2 = 0.f, pg3 = 0.f;
        if (tid < 48) {
            const float* pp = pre + (size_t)(ub * 256 + t) * N2 + dir * 3072 + c0 + ucell;
            pg0 = __ldg(pp + 0 * 768);
            pg1 = __ldg(pp + 1 * 768);
            pg2 = __ldg(pp + 2 * 768);
            pg3 = __ldg(pp + 3 * 768);
        }

        if (step == 0) {
#pragma unroll
            for (int q = 0; q < 3; q++)
                *(float4*)&shb[pb[q] * 768 + pj[q]] = make_float4(0.f, 0.f, 0.f, 0.f);
        } else {
            float4 v[3];
            bool d[3] = {false, false, false};
            const float* p0 = hseq + (size_t)(pb[0] * 256 + tp) * D2 + dir * HB + pj[0];
            const float* p1 = hseq + (size_t)(pb[1] * 256 + tp) * D2 + dir * HB + pj[1];
            const float* p2 = hseq + (size_t)(pb[2] * 256 + tp) * D2 + dir * HB + pj[2];
            do {
                if (!d[0]) { v[0] = ldcg4(p0); d[0] = valid4(v[0]); }
                if (!d[1]) { v[1] = ldcg4(p1); d[1] = valid4(v[1]); }
                if (!d[2]) { v[2] = ldcg4(p2); d[2] = valid4(v[2]); }
            } while (!(d[0] && d[1] && d[2]));
#pragma unroll
            for (int q = 0; q < 3; q++)
                *(float4*)&shb[pb[q] * 768 + pj[q]] = v[q];
        }
        __syncthreads();   // sync1: h staged

        // micro-GEMM: 6 rows x 4 batches per warp; k over lanes
        float acc[6][4];
#pragma unroll
        for (int i = 0; i < 6; i++)
#pragma unroll
            for (int b = 0; b < 4; b++) acc[i][b] = 0.f;
#pragma unroll
        for (int j = 0; j < 6; j++) {
            const int ko = j * 128 + ks * 4;
            float4 h0 = *(const float4*)(shb + 0 * 768 + ko);
            float4 h1 = *(const float4*)(shb + 1 * 768 + ko);
            float4 h2 = *(const float4*)(shb + 2 * 768 + ko);
            float4 h3 = *(const float4*)(shb + 3 * 768 + ko);
#pragma unroll
            for (int i = 0; i < 6; i++) {
                const float4 W = wreg[i][j];
                acc[i][0] += W.x*h0.x + W.y*h0.y + W.z*h0.z + W.w*h0.w;
                acc[i][1] += W.x*h1.x + W.y*h1.y + W.z*h1.z + W.w*h1.w;
                acc[i][2] += W.x*h2.x + W.y*h2.y + W.z*h2.z + W.w*h2.w;
                acc[i][3] += W.x*h3.x + W.y*h3.y + W.z*h3.z + W.w*h3.w;
            }
        }
#pragma unroll
        for (int o = 16; o; o >>= 1)
#pragma unroll
            for (int i = 0; i < 6; i++)
#pragma unroll
                for (int b = 0; b < 4; b++)
                    acc[i][b] += __shfl_xor_sync(0xffffffffu, acc[i][b], o);

        if (ks < 24) {
            const int i = ks >> 2, b = ks & 3;
            sgates[(6 * w + i) * 4 + b] = acc[i][b];
        }
        __syncthreads();   // sync2: gate sums visible

        if (tid < 48) {
            float xi = sgates[(0 * 12 + ucell) * 4 + ub] + pg0;
            float xf = sgates[(1 * 12 + ucell) * 4 + ub] + pg1;
            float xg = sgates[(2 * 12 + ucell) * 4 + ub] + pg2;
            float xo = sgates[(3 * 12 + ucell) * 4 + ub] + pg3;
            creg = sigf(xf) * creg + sigf(xi) * tanh_fast(xg);
            float h = sigf(xo) * tanh_fast(creg);
            const size_t oi = (size_t)(ub * 256 + t) * D2 + dir * HB + c0 + ucell;
            __stcg(&hseq[oi], h);                    // data IS the flag
            if (do_tanh) out2[oi] = tanhf(h);        // off the critical chain
        }
        // no third sync: sgates rewrites happen after next sync1;
        // sh buffer parity protects compute reads.
    }
}

// ---------------------------------------------------------------------------
__device__ __forceinline__ float blockReduceSum(float v, float* sr)
{
    __syncthreads();
#pragma unroll
    for (int o = 16; o; o >>= 1) v += __shfl_xor_sync(0xffffffffu, v, o);
    int lane = threadIdx.x & 31, w = threadIdx.x >> 5;
    if (lane == 0) sr[w] = v;
    __syncthreads();
    if (w == 0) {
        int nw = (blockDim.x + 31) >> 5;
        v = (lane < nw) ? sr[lane] : 0.f;
#pragma unroll
        for (int o = 16; o; o >>= 1) v += __shfl_xor_sync(0xffffffffu, v, o);
        if (lane == 0) sr[0] = v;
    }
    __syncthreads();
    return sr[0];
}

// scores + softmax: block per (b,q); thread = k.
__global__ __launch_bounds__(256)
void scores_kernel(const float* __restrict__ hq, const float* __restrict__ hk,
                   const float* __restrict__ w2, const float* __restrict__ b2p,
                   const float* __restrict__ am, const float* __restrict__ smk,
                   float* __restrict__ P)
{
    __shared__ float shq[768], sw2[768], shk[256 * 33], sr[32];
    const int tid = threadIdx.x, bq = blockIdx.x;
    const int b = bq >> 6, q = bq & 63;
    for (int i = tid; i < 768; i += 256) { shq[i] = hq[bq * 768 + i]; sw2[i] = w2[i]; }
    float acc = 0.f;
    for (int e0 = 0; e0 < 768; e0 += 32) {
        __syncthreads();
        for (int idx = tid; idx < 256 * 32; idx += 256) {
            int k = idx >> 5, e = idx & 31;
            shk[k * 33 + e] = hk[(size_t)((b << 8) + k) * 768 + e0 + e];
        }
        __syncthreads();
#pragma unroll 8
        for (int e = 0; e < 32; e++) {
            float v = shq[e0 + e] + shk[tid * 33 + e];
            acc += fmaxf(v, 0.f) * sw2[e0 + e];
        }
    }
    float score = acc + b2p[0];
    float m = am[b * 64 + q] * smk[b * 256 + tid];
    float a = (m == 0.f) ? 0.f : expf(score);
    float s = blockReduceSum(a, sr);
    P[bq * 256 + tid] = a / fmaxf(s, 2e-15f);
}

__global__ __launch_bounds__(256)
void adv_kernel(const float* __restrict__ tmpT, const float* __restrict__ act,
                const float* __restrict__ bias, float* __restrict__ adv)
{
    __shared__ float sa[768], sr[32];
    const int tid = threadIdx.x, bq = blockIdx.x;
    for (int i = tid; i < 768; i += 256) sa[i] = act[(size_t)bq * 768 + i];
    for (int l = 0; l < 3; l++) {
        float acc = 0.f;
        for (int h = tid; h < 768; h += 256)
            acc += tmpT[(size_t)bq * 2304 + l * 768 + h] * sa[h];
        float s = blockReduceSum(acc, sr);
        if (tid == 0) adv[bq * 3 + l] = s + bias[l];
    }
}

__global__ __launch_bounds__(256)
void final_kernel(const float* __restrict__ sf, const float* __restrict__ adv,
                  const float* __restrict__ valW, const float* __restrict__ valbp,
                  const float* __restrict__ am, float* __restrict__ out)
{
    __shared__ float sr[32];
    const int tid = threadIdx.x, b = blockIdx.x;
    float accv = 0.f;
    for (int d = tid; d < D2; d += 256) {
        float s = 0.f;
        for (int q = 0; q < 64; q++) s += sf[(size_t)(b * 64 + q) * D2 + d];
        accv += s * valW[d];
    }
    accv = blockReduceSum(accv, sr);
    float nv = (tid < 64) ? am[b * 64 + tid] : 0.f;
    nv = blockReduceSum(nv, sr);
    float asum = 0.f;
    for (int i = tid; i < 192; i += 256) asum += adv[b * 192 + i];
    asum = blockReduceSum(asum, sr);
    float val = accv / nv + valbp[0];
    float mean = asum / 192.f;
    for (int i = tid; i < 192; i += 256)
        out[b * 192 + i] = val + adv[b * 192 + i] - mean;
}

// ---------------------------------------------------------------------------
extern "C" void kernel_launch(void* const* d_in, const int* in_sizes, int n_in,
                              void* d_out, int out_size)
{
    const float* states  = (const float*)d_in[0];
    const float* smask   = (const float*)d_in[1];
    const float* actions = (const float*)d_in[2];
    const float* amask   = (const float*)d_in[3];
    const float* Wih0    = (const float*)d_in[4];
    const float* Whh0    = (const float*)d_in[5];
    const float* b0      = (const float*)d_in[6];
    const float* Wih12   = (const float*)d_in[7];
    const float* Whh12   = (const float*)d_in[8];
    const float* b12     = (const float*)d_in[9];
    const float* attnW1  = (const float*)d_in[10];
    const float* attnb1  = (const float*)d_in[11];
    const float* attnW2  = (const float*)d_in[12];
    const float* attnb2  = (const float*)d_in[13];
    const float* valW    = (const float*)d_in[14];
    const float* valb    = (const float*)d_in[15];
    const float* weight  = (const float*)d_in[16];
    const float* bias    = (const float*)d_in[17];
    float* out = (float*)d_out;

    float *pre, *hseq, *seqA, *hq, *hk, *P, *sf, *tmpT, *adv;
    cudaGetSymbolAddress((void**)&pre,  g_pre);
    cudaGetSymbolAddress((void**)&hseq, g_hseq);
    cudaGetSymbolAddress((void**)&seqA, g_seqA);
    cudaGetSymbolAddress((void**)&hq,   g_hq);
    cudaGetSymbolAddress((void**)&hk,   g_hk);
    cudaGetSymbolAddress((void**)&P,    g_P);
    cudaGetSymbolAddress((void**)&sf,   g_sf);
    cudaGetSymbolAddress((void**)&tmpT, g_tmpT);
    cudaGetSymbolAddress((void**)&adv,  g_adv);

    const int n4 = 1024 * D2 / 4;

    // layer 0
    poison_kernel<<<(n4 + 255) / 256, 256>>>((float4*)hseq, n4);
    tf32gemm_abT<<<dim3(48, 8), 256>>>(states, HB, Wih0, HB, b0, pre, N2, HB);
    rec_kernel<<<RECB, REC2T>>>(pre, Whh0, hseq, nullptr, 256, 0);
    // layer 1
    tf32gemm_abT<<<dim3(48, 8), 256>>>(hseq, D2, Wih12, D2, b12, pre, N2, D2);
    poison_kernel<<<(n4 + 255) / 256, 256>>>((float4*)hseq, n4);
    rec_kernel<<<RECB, REC2T>>>(pre, Whh12, hseq, nullptr, 256, 0);
    // layer 2 (raw h -> hseq for dataflow, tanh(h) -> seqA for attention)
    tf32gemm_abT<<<dim3(48, 8), 256>>>(hseq, D2, Wih12 + (size_t)2 * 3072 * D2, D2,
                                       b12 + 6144, pre, N2, D2);
    poison_kernel<<<(n4 + 255) / 256, 256>>>((float4*)hseq, n4);
    rec_kernel<<<RECB, REC2T>>>(pre, Whh12 + (size_t)2 * 3072 * HB, hseq, seqA, 256, 1);
    // attention projections
    tf32gemm_abT<<<dim3(6, 2), 256>>>(actions, HB, attnW1, 2304, attnb1, hq, HB, HB);
    tf32gemm_abT<<<dim3(6, 8), 256>>>(seqA, D2, attnW1 + HB, 2304, nullptr, hk, HB, D2);
    // scores + softmax
    scores_kernel<<<256, 256>>>(hq, hk, attnW2, attnb2, amask, smask, P);
    // states_feat = P @ out  (batched per b)
    gemm_ab64<<<dim3(24, 1, 4), 256>>>(P, 256, (size_t)64 * 256,
                                       seqA, D2, (size_t)256 * D2,
                                       sf, D2, (size_t)64 * D2, 256);
    // tmpT = sf @ weight^T
    tf32gemm_abT<<<dim3(18, 2), 256>>>(sf, D2, weight, D2, nullptr, tmpT, 2304, D2);
    // adv + final
    adv_kernel<<<256, 256>>>(tmpT, actions, bias, adv);
    final_kernel<<<4, 256>>>(sf, adv, valW, valb, amask, out);
}

// round 16
// speedup vs baseline: 1.7319x; 1.7319x over previous
#include <cuda_runtime.h>
#include <cstdint>

#define HB 768
#define N2 6144
#define D2 1536
#define RECB 128
#define REC2T 256
#define SENT 0x7FC00001u

// ----------------------------- scratch (device globals; allocation-free) ----
__device__ float g_pre [1024 * N2];
__device__ float g_hseq[1024 * D2];   // raw-h sequence: comm + layer output
__device__ float g_seqA[1024 * D2];   // tanh(h) of layer 2
__device__ float g_hq  [256 * HB];
__device__ float g_hk  [1024 * HB];
__device__ float g_P   [256 * 256];
__device__ float g_sf  [256 * D2];
__device__ float g_tmpT[256 * 2304];
__device__ float g_adv [256 * 3];

// ---------------------------------------------------------------------------
// TF32 tensor-core GEMM 128x128x16: C = A @ B^T (+bias). Double-buffered.
// (R10 body — also serves as the cross-round clock reference.)
// ---------------------------------------------------------------------------
__device__ __forceinline__ uint32_t f2tf32(float f)
{
    uint32_t u;
    asm("cvt.rna.tf32.f32 %0, %1;" : "=r"(u) : "f"(f));
    return u;
}
__device__ __forceinline__ void mma_tf32(float* c, const uint32_t* a,
                                         uint32_t b0, uint32_t b1)
{
    asm volatile(
        "mma.sync.aligned.m16n8k8.row.col.f32.tf32.tf32.f32 "
        "{%0,%1,%2,%3}, {%4,%5,%6,%7}, {%8,%9}, {%0,%1,%2,%3};\n"
        : "+f"(c[0]), "+f"(c[1]), "+f"(c[2]), "+f"(c[3])
        : "r"(a[0]), "r"(a[1]), "r"(a[2]), "r"(a[3]), "r"(b0), "r"(b1));
}

__global__ __launch_bounds__(256, 2)
void tf32gemm_abT(const float* __restrict__ A, int lda,
                  const float* __restrict__ B, int ldb,
                  const float* __restrict__ bias,
                  float* __restrict__ C, int ldc, int K)
{
    __shared__ uint32_t As[2][16][136];
    __shared__ uint32_t Bs[2][16][136];
    const int tid = threadIdx.x;
    const int m0 = blockIdx.y * 128, n0 = blockIdx.x * 128;
    const int warp = tid >> 5, lane = tid & 31;
    const int wm = warp >> 1, wn = warp & 1;
    const int gid = lane >> 2, tig = lane & 3;
    const int lrow = tid >> 2, lk = (tid & 3) * 4;
    const int sxor = ((lk >> 2) & 3) << 3;
    const int c0a = lrow ^ sxor, c1a = (64 + lrow) ^ sxor;

    float c[2][8][4];
#pragma unroll
    for (int mt = 0; mt < 2; mt++)
#pragma unroll
        for (int nt = 0; nt < 8; nt++)
#pragma unroll
            for (int q = 0; q < 4; q++) c[mt][nt][q] = 0.f;

    const float* Ap0 = A + (size_t)(m0 + lrow) * lda + lk;
    const float* Ap1 = A + (size_t)(m0 + 64 + lrow) * lda + lk;
    const float* Bp0 = B + (size_t)(n0 + lrow) * ldb + lk;
    const float* Bp1 = B + (size_t)(n0 + 64 + lrow) * ldb + lk;

#define STAGE(BUF, A0, A1, B0, B1) do {                                    \
    As[BUF][lk+0][c0a] = f2tf32(A0.x); As[BUF][lk+1][c0a] = f2tf32(A0.y);  \
    As[BUF][lk+2][c0a] = f2tf32(A0.z); As[BUF][lk+3][c0a] = f2tf32(A0.w);  \
    As[BUF][lk+0][c1a] = f2tf32(A1.x); As[BUF][lk+1][c1a] = f2tf32(A1.y);  \
    As[BUF][lk+2][c1a] = f2tf32(A1.z); As[BUF][lk+3][c1a] = f2tf32(A1.w);  \
    Bs[BUF][lk+0][c0a] = f2tf32(B0.x); Bs[BUF][lk+1][c0a] = f2tf32(B0.y);  \
    Bs[BUF][lk+2][c0a] = f2tf32(B0.z); Bs[BUF][lk+3][c0a] = f2tf32(B0.w);  \
    Bs[BUF][lk+0][c1a] = f2tf32(B1.x); Bs[BUF][lk+1][c1a] = f2tf32(B1.y);  \
    Bs[BUF][lk+2][c1a] = f2tf32(B1.z); Bs[BUF][lk+3][c1a] = f2tf32(B1.w);  \
} while (0)

    float4 a0 = *(const float4*)(Ap0);
    float4 a1 = *(const float4*)(Ap1);
    float4 b0 = *(const float4*)(Bp0);
    float4 b1 = *(const float4*)(Bp1);
    STAGE(0, a0, a1, b0, b1);
    __syncthreads();

    const int nT = K >> 4;
    for (int t = 0; t < nT; t++) {
        const int buf = t & 1;
        if (t + 1 < nT) {
            const int k0 = (t + 1) << 4;
            a0 = *(const float4*)(Ap0 + k0);
            a1 = *(const float4*)(Ap1 + k0);
            b0 = *(const float4*)(Bp0 + k0);
            b1 = *(const float4*)(Bp1 + k0);
        }
#pragma unroll
        for (int ks = 0; ks < 2; ks++) {
            const int r0 = ks * 8 + tig;
            const int r1 = ks * 8 + 4 + tig;
            const int x0 = ((r0 >> 2) & 3) << 3;
            const int x1 = ((r1 >> 2) & 3) << 3;
            uint32_t af[2][4];
#pragma unroll
            for (int mt = 0; mt < 2; mt++) {
                const int mb = wm * 32 + mt * 16;
                af[mt][0] = As[buf][r0][(mb + gid) ^ x0];
                af[mt][1] = As[buf][r0][(mb + 8 + gid) ^ x0];
                af[mt][2] = As[buf][r1][(mb + gid) ^ x1];
                af[mt][3] = As[buf][r1][(mb + 8 + gid) ^ x1];
            }
#pragma unroll
            for (int nt = 0; nt < 8; nt++) {
                const int nb = wn * 64 + nt * 8;
                uint32_t bf0 = Bs[buf][r0][(nb + gid) ^ x0];
                uint32_t bf1 = Bs[buf][r1][(nb + gid) ^ x1];
                mma_tf32(c[0][nt], af[0], bf0, bf1);
                mma_tf32(c[1][nt], af[1], bf0, bf1);
            }
        }
        if (t + 1 < nT) {
            STAGE(buf ^ 1, a0, a1, b0, b1);
            __syncthreads();
        }
    }
#undef STAGE

#pragma unroll
    for (int mt = 0; mt < 2; mt++) {
        const int row = m0 + wm * 32 + mt * 16 + gid;
#pragma unroll
        for (int nt = 0; nt < 8; nt++) {
            const int col = n0 + wn * 64 + nt * 8 + tig * 2;
            float bv0 = bias ? bias[col] : 0.f;
            float bv1 = bias ? bias[col + 1] : 0.f;
            float2 v0 = make_float2(c[mt][nt][0] + bv0, c[mt][nt][1] + bv1);
            float2 v1 = make_float2(c[mt][nt][2] + bv0, c[mt][nt][3] + bv1);
            *(float2*)&C[(size_t)row * ldc + col] = v0;
            *(float2*)&C[(size_t)(row + 8) * ldc + col] = v1;
        }
    }
}

// ---------------------------------------------------------------------------
// Batched GEMM 64x64x16: C = A @ B (for P @ out).
// ---------------------------------------------------------------------------
__global__ __launch_bounds__(256)
void gemm_ab64(const float* __restrict__ Ab, int lda, size_t strA,
               const float* __restrict__ Bb, int ldb, size_t strB,
               float* __restrict__ Cb, int ldc, size_t strC, int K)
{
    const float* A = Ab + strA * blockIdx.z;
    const float* B = Bb + strB * blockIdx.z;
    float* C = Cb + strC * blockIdx.z;
    __shared__ float As[16][68];
    __shared__ float Bs[16][68];
    const int tid = threadIdx.x;
    const int m0 = blockIdx.y * 64, n0 = blockIdx.x * 64;
    const int tx = tid & 15, ty = tid >> 4;
    const int lrow = tid >> 2, lk = (tid & 3) * 4;
    const int bkk = tid >> 4, bnq = (tid & 15) * 4;

    float acc[4][4];
#pragma unroll
    for (int i = 0; i < 4; i++)
#pragma unroll
        for (int j = 0; j < 4; j++) acc[i][j] = 0.f;

    for (int k0 = 0; k0 < K; k0 += 16) {
        float4 a0 = *(const float4*)&A[(size_t)(m0 + lrow) * lda + k0 + lk];
        float4 b0 = *(const float4*)&B[(size_t)(k0 + bkk) * ldb + n0 + bnq];
        __syncthreads();
        As[lk+0][lrow]=a0.x; As[lk+1][lrow]=a0.y; As[lk+2][lrow]=a0.z; As[lk+3][lrow]=a0.w;
        *(float4*)&Bs[bkk][bnq] = b0;
        __syncthreads();
#pragma unroll
        for (int kk = 0; kk < 16; kk++) {
            float ar[4], br[4];
            *(float4*)&ar[0] = *(const float4*)&As[kk][ty * 4];
            *(float4*)&br[0] = *(const float4*)&Bs[kk][tx * 4];
#pragma unroll
            for (int i = 0; i < 4; i++)
#pragma unroll
                for (int j = 0; j < 4; j++) acc[i][j] += ar[i] * br[j];
        }
    }
#pragma unroll
    for (int i = 0; i < 4; i++) {
        float4 v = make_float4(acc[i][0], acc[i][1], acc[i][2], acc[i][3]);
        *(float4*)&C[(size_t)(m0 + ty * 4 + i) * ldc + n0 + tx * 4] = v;
    }
}

// ---------------------------------------------------------------------------
__global__ void poison_kernel(float4* __restrict__ p, int n4)
{
    int i = blockIdx.x * blockDim.x + threadIdx.x;
    float s = __uint_as_float(SENT);
    if (i < n4) p[i] = make_float4(s, s, s, s);
}

// ---------------------------------------------------------------------------
// Persistent BiLSTM recurrence v5 (R10, byte-identical — measured best).
// 128 CTAs x 256 thr (8 warps). CTA: dir = bx>>6, cells [c0,c0+12).
// Row r = g*12 + cell (48 rows). Warp w owns rows [6w, 6w+6); lane ks holds
// k-chunks {j*128 + ks*4} -> wreg[6][6] float4 = 144 regs (cap 255 @256thr).
// Per step smem traffic = h only. Gate sums exchanged via sgates smem.
// ---------------------------------------------------------------------------
__device__ __forceinline__ float sigf(float x) { return 1.f / (1.f + expf(-x)); }

__device__ __forceinline__ float4 ldcg4(const float* p)
{
    float4 v;
    asm volatile("ld.global.cg.v4.f32 {%0,%1,%2,%3}, [%4];"
                 : "=f"(v.x), "=f"(v.y), "=f"(v.z), "=f"(v.w) : "l"(p));
    return v;
}
__device__ __forceinline__ bool valid4(float4 v)
{
    return (__float_as_uint(v.x) != SENT) & (__float_as_uint(v.y) != SENT) &
           (__float_as_uint(v.z) != SENT) & (__float_as_uint(v.w) != SENT);
}

__global__ __launch_bounds__(REC2T, 1)
void rec_kernel(const float* __restrict__ pre,   // [1024][6144]
                const float* __restrict__ whh,   // [2][3072][768]
                float* __restrict__ hseq,        // [1024][1536] raw h (poisoned)
                float* __restrict__ out2,        // tanh(h) when do_tanh
                int T, int do_tanh)
{
    __shared__ float sh[2][4 * 768];
    __shared__ float sgates[48 * 4];

    const int tid = threadIdx.x;
    const int bx  = blockIdx.x;
    const int dir = bx >> 6;
    const int c0  = (bx & 63) * 12;
    const int w   = tid >> 5, ks = tid & 31;

    // weights -> registers: warp w owns rows 6w..6w+5 (row = g*12+cell);
    // lane ks holds k = j*128 + ks*4 .. +3 for j=0..5.
    float4 wreg[6][6];
#pragma unroll
    for (int i = 0; i < 6; i++) {
        const int r = 6 * w + i;
        const int g = r / 12, jj = r - g * 12;
        const float* wp = whh + ((size_t)dir * 3072 + g * 768 + c0 + jj) * 768;
#pragma unroll
        for (int j = 0; j < 6; j++)
            wreg[i][j] = *(const float4*)(wp + j * 128 + ks * 4);
    }

    // poll assignment: 768 float4s of h (4 batches x 192), 3 per thread
    int pb[3], pj[3];
#pragma unroll
    for (int q = 0; q < 3; q++) {
        int f = tid + q * REC2T;
        pb[q] = f / 192;
        pj[q] = (f - pb[q] * 192) * 4;
    }

    // update-thread identity (tid < 48): cell = tid>>2, batch = tid&3
    const int ucell = tid >> 2, ub = tid & 3;

    float creg = 0.f;
    for (int step = 0; step < T; step++) {
        const int t  = (dir == 0) ? step : (T - 1 - step);
        const int tp = (dir == 0) ? t - 1 : t + 1;
        float* shb = sh[step & 1];

        // update threads prefetch their own pre-activations (4 gates)
        float pg0 = 0.f, pg1 = 0.f, pg2 = 0.f, pg3 = 0.f;
        if (tid < 48) {
            const float* pp = pre + (size_t)(ub * 256 + t) * N2 + dir * 3072 + c0 + ucell;
            pg0 = __ldg(pp + 0 * 768);
            pg1 = __ldg(pp + 1 * 768);
            pg2 = __ldg(pp + 2 * 768);
            pg3 = __ldg(pp + 3 * 768);
        }

        if (step == 0) {
#pragma unroll
            for (int q = 0; q < 3; q++)
                *(float4*)&shb[pb[q] * 768 + pj[q]] = make_float4(0.f, 0.f, 0.f, 0.f);
        } else {
            float4 v[3];
            bool d[3] = {false, false, false};
            const float* p0 = hseq + (size_t)(pb[0] * 256 + tp) * D2 + dir * HB + pj[0];
            const float* p1 = hseq + (size_t)(pb[1] * 256 + tp) * D2 + dir * HB + pj[1];
            const float* p2 = hseq + (size_t)(pb[2] * 256 + tp) * D2 + dir * HB + pj[2];
            do {
                if (!d[0]) { v[0] = ldcg4(p0); d[0] = valid4(v[0]); }
                if (!d[1]) { v[1] = ldcg4(p1); d[1] = valid4(v[1]); }
                if (!d[2]) { v[2] = ldcg4(p2); d[2] = valid4(v[2]); }
            } while (!(d[0] && d[1] && d[2]));
#pragma unroll
            for (int q = 0; q < 3; q++)
                *(float4*)&shb[pb[q] * 768 + pj[q]] = v[q];
        }
        __syncthreads();   // sync1: h staged

        // micro-GEMM: 6 rows x 4 batches per warp; k over lanes
        float acc[6][4];
#pragma unroll
        for (int i = 0; i < 6; i++)
#pragma unroll
            for (int b = 0; b < 4; b++) acc[i][b] = 0.f;
#pragma unroll
        for (int j = 0; j < 6; j++) {
            const int ko = j * 128 + ks * 4;
            float4 h0 = *(const float4*)(shb + 0 * 768 + ko);
            float4 h1 = *(const float4*)(shb + 1 * 768 + ko);
            float4 h2 = *(const float4*)(shb + 2 * 768 + ko);
            float4 h3 = *(const float4*)(shb + 3 * 768 + ko);
#pragma unroll
            for (int i = 0; i < 6; i++) {
                const float4 W = wreg[i][j];
                acc[i][0] += W.x*h0.x + W.y*h0.y + W.z*h0.z + W.w*h0.w;
                acc[i][1] += W.x*h1.x + W.y*h1.y + W.z*h1.z + W.w*h1.w;
                acc[i][2] += W.x*h2.x + W.y*h2.y + W.z*h2.z + W.w*h2.w;
                acc[i][3] += W.x*h3.x + W.y*h3.y + W.z*h3.z + W.w*h3.w;
            }
        }
#pragma unroll
        for (int o = 16; o; o >>= 1)
#pragma unroll
            for (int i = 0; i < 6; i++)
#pragma unroll
                for (int b = 0; b < 4; b++)
                    acc[i][b] += __shfl_xor_sync(0xffffffffu, acc[i][b], o);

        if (ks < 24) {
            const int i = ks >> 2, b = ks & 3;
            sgates[(6 * w + i) * 4 + b] = acc[i][b];
        }
        __syncthreads();   // sync2: gate sums visible

        if (tid < 48) {
            float xi = sgates[(0 * 12 + ucell) * 4 + ub] + pg0;
            float xf = sgates[(1 * 12 + ucell) * 4 + ub] + pg1;
            float xg = sgates[(2 * 12 + ucell) * 4 + ub] + pg2;
            float xo = sgates[(3 * 12 + ucell) * 4 + ub] + pg3;
            creg = sigf(xf) * creg + sigf(xi) * tanhf(xg);
            float h = sigf(xo) * tanhf(creg);
            const size_t oi = (size_t)(ub * 256 + t) * D2 + dir * HB + c0 + ucell;
            __stcg(&hseq[oi], h);                    // data IS the flag
            if (do_tanh) out2[oi] = tanhf(h);
        }
        // no third sync: sgates rewrites happen after next sync1;
        // sh buffer parity protects compute reads.
    }
}

// ---------------------------------------------------------------------------
__device__ __forceinline__ float blockReduceSum(float v, float* sr)
{
    __syncthreads();
#pragma unroll
    for (int o = 16; o; o >>= 1) v += __shfl_xor_sync(0xffffffffu, v, o);
    int lane = threadIdx.x & 31, w = threadIdx.x >> 5;
    if (lane == 0) sr[w] = v;
    __syncthreads();
    if (w == 0) {
        int nw = (blockDim.x + 31) >> 5;
        v = (lane < nw) ? sr[lane] : 0.f;
#pragma unroll
        for (int o = 16; o; o >>= 1) v += __shfl_xor_sync(0xffffffffu, v, o);
        if (lane == 0) sr[0] = v;
    }
    __syncthreads();
    return sr[0];
}

// scores + softmax: block per (b,q); thread = k.
__global__ __launch_bounds__(256)
void scores_kernel(const float* __restrict__ hq, const float* __restrict__ hk,
                   const float* __restrict__ w2, const float* __restrict__ b2p,
                   const float* __restrict__ am, const float* __restrict__ smk,
                   float* __restrict__ P)
{
    __shared__ float shq[768], sw2[768], shk[256 * 33], sr[32];
    const int tid = threadIdx.x, bq = blockIdx.x;
    const int b = bq >> 6, q = bq & 63;
    for (int i = tid; i < 768; i += 256) { shq[i] = hq[bq * 768 + i]; sw2[i] = w2[i]; }
    float acc = 0.f;
    for (int e0 = 0; e0 < 768; e0 += 32) {
        __syncthreads();
        for (int idx = tid; idx < 256 * 32; idx += 256) {
            int k = idx >> 5, e = idx & 31;
            shk[k * 33 + e] = hk[(size_t)((b << 8) + k) * 768 + e0 + e];
        }
        __syncthreads();
#pragma unroll 8
        for (int e = 0; e < 32; e++) {
            float v = shq[e0 + e] + shk[tid * 33 + e];
            acc += fmaxf(v, 0.f) * sw2[e0 + e];
        }
    }
    float score = acc + b2p[0];
    float m = am[b * 64 + q] * smk[b * 256 + tid];
    float a = (m == 0.f) ? 0.f : expf(score);
    float s = blockReduceSum(a, sr);
    P[bq * 256 + tid] = a / fmaxf(s, 2e-15f);
}

__global__ __launch_bounds__(256)
void adv_kernel(const float* __restrict__ tmpT, const float* __restrict__ act,
                const float* __restrict__ bias, float* __restrict__ adv)
{
    __shared__ float sa[768], sr[32];
    const int tid = threadIdx.x, bq = blockIdx.x;
    for (int i = tid; i < 768; i += 256) sa[i] = act[(size_t)bq * 768 + i];
    for (int l = 0; l < 3; l++) {
        float acc = 0.f;
        for (int h = tid; h < 768; h += 256)
            acc += tmpT[(size_t)bq * 2304 + l * 768 + h] * sa[h];
        float s = blockReduceSum(acc, sr);
        if (tid == 0) adv[bq * 3 + l] = s + bias[l];
    }
}

__global__ __launch_bounds__(256)
void final_kernel(const float* __restrict__ sf, const float* __restrict__ adv,
                  const float* __restrict__ valW, const float* __restrict__ valbp,
                  const float* __restrict__ am, float* __restrict__ out)
{
    __shared__ float sr[32];
    const int tid = threadIdx.x, b = blockIdx.x;
    float accv = 0.f;
    for (int d = tid; d < D2; d += 256) {
        float s = 0.f;
        for (int q = 0; q < 64; q++) s += sf[(size_t)(b * 64 + q) * D2 + d];
        accv += s * valW[d];
    }
    accv = blockReduceSum(accv, sr);
    float nv = (tid < 64) ? am[b * 64 + tid] : 0.f;
    nv = blockReduceSum(nv, sr);
    float asum = 0.f;
    for (int i = tid; i < 192; i += 256) asum += adv[b * 192 + i];
    asum = blockReduceSum(asum, sr);
    float val = accv / nv + valbp[0];
    float mean = asum / 192.f;
    for (int i = tid; i < 192; i += 256)
        out[b * 192 + i] = val + adv[b * 192 + i] - mean;
}

// ---------------------------------------------------------------------------
extern "C" void kernel_launch(void* const* d_in, const int* in_sizes, int n_in,
                              void* d_out, int out_size)
{
    const float* states  = (const float*)d_in[0];
    const float* smask   = (const float*)d_in[1];
    const float* actions = (const float*)d_in[2];
    const float* amask   = (const float*)d_in[3];
    const float* Wih0    = (const float*)d_in[4];
    const float* Whh0    = (const float*)d_in[5];
    const float* b0      = (const float*)d_in[6];
    const float* Wih12   = (const float*)d_in[7];
    const float* Whh12   = (const float*)d_in[8];
    const float* b12     = (const float*)d_in[9];
    const float* attnW1  = (const float*)d_in[10];
    const float* attnb1  = (const float*)d_in[11];
    const float* attnW2  = (const float*)d_in[12];
    const float* attnb2  = (const float*)d_in[13];
    const float* valW    = (const float*)d_in[14];
    const float* valb    = (const float*)d_in[15];
    const float* weight  = (const float*)d_in[16];
    const float* bias    = (const float*)d_in[17];
    float* out = (float*)d_out;

    float *pre, *hseq, *seqA, *hq, *hk, *P, *sf, *tmpT, *adv;
    cudaGetSymbolAddress((void**)&pre,  g_pre);
    cudaGetSymbolAddress((void**)&hseq, g_hseq);
    cudaGetSymbolAddress((void**)&seqA, g_seqA);
    cudaGetSymbolAddress((void**)&hq,   g_hq);
    cudaGetSymbolAddress((void**)&hk,   g_hk);
    cudaGetSymbolAddress((void**)&P,    g_P);
    cudaGetSymbolAddress((void**)&sf,   g_sf);
    cudaGetSymbolAddress((void**)&tmpT, g_tmpT);
    cudaGetSymbolAddress((void**)&adv,  g_adv);

    const int n4 = 1024 * D2 / 4;

    // layer 0
    poison_kernel<<<(n4 + 255) / 256, 256>>>((float4*)hseq, n4);
    tf32gemm_abT<<<dim3(48, 8), 256>>>(states, HB, Wih0, HB, b0, pre, N2, HB);
    rec_kernel<<<RECB, REC2T>>>(pre, Whh0, hseq, nullptr, 256, 0);
    // layer 1
    tf32gemm_abT<<<dim3(48, 8), 256>>>(hseq, D2, Wih12, D2, b12, pre, N2, D2);
    poison_kernel<<<(n4 + 255) / 256, 256>>>((float4*)hseq, n4);
    rec_kernel<<<RECB, REC2T>>>(pre, Whh12, hseq, nullptr, 256, 0);
    // layer 2 (raw h -> hseq for dataflow, tanh(h) -> seqA for attention)
    tf32gemm_abT<<<dim3(48, 8), 256>>>(hseq, D2, Wih12 + (size_t)2 * 3072 * D2, D2,
                                       b12 + 6144, pre, N2, D2);
    poison_kernel<<<(n4 + 255) / 256, 256>>>((float4*)hseq, n4);
    rec_kernel<<<RECB, REC2T>>>(pre, Whh12 + (size_t)2 * 3072 * HB, hseq, seqA, 256, 1);
    // attention projections
    tf32gemm_abT<<<dim3(6, 2), 256>>>(actions, HB, attnW1, 2304, attnb1, hq, HB, HB);
    tf32gemm_abT<<<dim3(6, 8), 256>>>(seqA, D2, attnW1 + HB, 2304, nullptr, hk, HB, D2);
    // scores + softmax
    scores_kernel<<<256, 256>>>(hq, hk, attnW2, attnb2, amask, smask, P);
    // states_feat = P @ out  (batched per b)
    gemm_ab64<<<dim3(24, 1, 4), 256>>>(P, 256, (size_t)64 * 256,
                                       seqA, D2, (size_t)256 * D2,
                                       sf, D2, (size_t)64 * D2, 256);
    // tmpT = sf @ weight^T
    tf32gemm_abT<<<dim3(18, 2), 256>>>(sf, D2, weight, D2, nullptr, tmpT, 2304, D2);
    // adv + final
    adv_kernel<<<256, 256>>>(tmpT, actions, bias, adv);
    final_kernel<<<4, 256>>>(sf, adv, valW, valb, amask, out);
}